// round 6
// baseline (speedup 1.0000x reference)
#include <cuda_runtime.h>
#include <cstdint>

// Problem constants (fixed by the dataset)
#define BATCH 2
#define NPTS  16384
#define CH    64
#define SPTS  4096        // npoint
#define KNB   32          // nsample
#define R2    0.16f       // 0.4^2
#define OUTC  128

#define N_XYZ_OUT  (BATCH*SPTS*3)          // 24576
#define N_FEAT_OUT (BATCH*OUTC*SPTS)       // 1048576
#define OFF_FEAT   N_XYZ_OUT
#define OFF_SAMP   (N_XYZ_OUT + N_FEAT_OUT)

// Scratch (no allocation allowed -> device globals)
__device__ int g_idx[BATCH*SPTS*KNB];
__device__ __align__(16) float g_featT[(size_t)BATCH*NPTS*CH];
__device__ __align__(16) float4 g_xyzw[BATCH*NPTS];

// ---------------------------------------------------------------------------
// f32x2 packed-FMA helpers (sm_103a FFMA2)
// ---------------------------------------------------------------------------
__device__ __forceinline__ void ffma2(uint64_t& acc, uint64_t a, uint64_t b) {
    asm("fma.rn.f32x2 %0, %1, %2, %3;" : "=l"(acc) : "l"(a), "l"(b), "l"(acc));
}
__device__ __forceinline__ uint64_t pack2(float v) {
    uint64_t r;
    asm("mov.b64 %0, {%1, %1};" : "=l"(r) : "r"(__float_as_uint(v)));
    return r;
}
__device__ __forceinline__ void unpack2(uint64_t p, float& lo, float& hi) {
    unsigned a, b;
    asm("mov.b64 {%0, %1}, %2;" : "=r"(a), "=r"(b) : "l"(p));
    lo = __uint_as_float(a); hi = __uint_as_float(b);
}

// ---------------------------------------------------------------------------
// Kernel 0: pack xyz + precomputed squared norm into float4
// ---------------------------------------------------------------------------
__global__ void prep_kernel(const float* __restrict__ xyz) {
    int i = blockIdx.x * blockDim.x + threadIdx.x;
    if (i >= BATCH * NPTS) return;
    float px = xyz[i*3+0], py = xyz[i*3+1], pz = xyz[i*3+2];
    float pp = px*px + py*py + pz*pz;   // same expression as before (bit-stable)
    g_xyzw[i] = make_float4(px, py, pz, pp);
}

// ---------------------------------------------------------------------------
// Kernel 1: ball query. One warp per centroid, early exit at 32 hits.
// ---------------------------------------------------------------------------
__global__ void bq_kernel() {
    int w    = (blockIdx.x * blockDim.x + threadIdx.x) >> 5;
    int lane = threadIdx.x & 31;
    if (w >= BATCH * SPTS) return;
    int b = w / SPTS, s = w % SPTS;
    const float4* xb4 = g_xyzw + (size_t)b * NPTS;
    float4 q = xb4[s];
    int* idx = g_idx + (size_t)w * KNB;
    int cnt = 0;
    int firstIdx = 0;
    bool haveFirst = false;
    for (int j0 = 0; j0 < NPTS && cnt < KNB; j0 += 32) {
        int j = j0 + lane;
        float4 p = xb4[j];
        float dot = q.x*p.x + q.y*p.y + q.z*p.z;
        float d2  = q.w + p.w - 2.0f*dot;   // same formula as reference
        bool hit = d2 < R2;
        unsigned mask = __ballot_sync(0xffffffffu, hit);
        if (mask && !haveFirst) {
            firstIdx = __shfl_sync(0xffffffffu, j, __ffs(mask) - 1);
            haveFirst = true;
        }
        int pos = cnt + __popc(mask & ((1u << lane) - 1u));
        if (hit && pos < KNB) idx[pos] = j;
        cnt += __popc(mask);
    }
    if (cnt < KNB && lane >= cnt) idx[lane] = firstIdx;
}

// ---------------------------------------------------------------------------
// Kernel 2: transpose features [B,C,N] -> [B,N,C]
// ---------------------------------------------------------------------------
__global__ void transpose_kernel(const float* __restrict__ f) {
    __shared__ float tile[32][33];
    int b  = blockIdx.z;
    int c0 = blockIdx.y * 32;
    int n0 = blockIdx.x * 32;
    int tx = threadIdx.x, ty = threadIdx.y;
    const float* src = f + ((size_t)b * CH) * NPTS;
    #pragma unroll
    for (int r = ty; r < 32; r += 8)
        tile[r][tx] = src[(size_t)(c0 + r) * NPTS + n0 + tx];
    __syncthreads();
    float* dst = g_featT + ((size_t)b * NPTS) * CH;
    #pragma unroll
    for (int r = ty; r < 32; r += 8)
        dst[(size_t)(n0 + r) * CH + c0 + tx] = tile[tx][r];
}

// ---------------------------------------------------------------------------
// Kernel 3: trivial outputs
// ---------------------------------------------------------------------------
__global__ void misc_kernel(const float* __restrict__ xyz, float* __restrict__ out) {
    int i = blockIdx.x * blockDim.x + threadIdx.x;
    if (i < N_XYZ_OUT) {
        int b = i / (SPTS * 3), r = i % (SPTS * 3);
        out[i] = xyz[(size_t)b * NPTS * 3 + r];
    }
    if (i < BATCH * SPTS) {
        out[OFF_SAMP + i] = (float)(i % SPTS);
    }
}

// ---------------------------------------------------------------------------
// Kernel 4: gather + 3-layer MLP + maxpool.
// One 256-thread block handles TWO centroids per iteration (64 k-rows).
// f32x2 packed FMAs. W1/W2/biases in smem; W3 via warp-uniform global loads.
// ---------------------------------------------------------------------------
#define MLP_THREADS 256
#define NK      64            // 2 groups * 32 neighbors
#define STRIDE  66            // row stride for activation tiles

// dynamic smem layout (floats)
#define OFF_W1  0                        // 67*64 = 4288
#define OFF_W2  (OFF_W1 + 67*64)         // +4096
#define OFF_B1  (OFF_W2 + 64*64)         // 8384
#define OFF_B2  (OFF_B1 + 64)
#define OFF_B3  (OFF_B2 + 64)
#define OFF_A   (OFF_B3 + 128)           // bufA: 67 rows * 66
#define OFF_BB  (OFF_A + 67*STRIDE)      // bufB: 64 rows * 66
#define SMEM_FLOATS (OFF_BB + 64*STRIDE)
#define SMEM_BYTES  (SMEM_FLOATS * 4)    // ~69.1 KB -> 3 CTAs/SM

__global__ void __launch_bounds__(MLP_THREADS, 3)
mlp_kernel(const float* __restrict__ W1, const float* __restrict__ b1,
           const float* __restrict__ W2, const float* __restrict__ b2,
           const float* __restrict__ W3, const float* __restrict__ b3,
           float* __restrict__ out) {
    extern __shared__ float sm[];
    __shared__ int sidx[NK];
    int t = threadIdx.x;
    // stage W1, W2, biases once
    for (int i = t; i < 67*64; i += MLP_THREADS) sm[OFF_W1 + i] = W1[i];
    for (int i = t; i < 64*64; i += MLP_THREADS) sm[OFF_W2 + i] = W2[i];
    if (t < 64)  sm[OFF_B1 + t] = b1[t];
    if (t < 64)  sm[OFF_B2 + t] = b2[t];
    if (t < 128) sm[OFF_B3 + t] = b3[t];
    __syncthreads();

    float* bufA = sm + OFF_A;
    float* bufB = sm + OFF_BB;
    int lane = t & 31;

    const int niter = (BATCH * SPTS) / 2;   // 4096 double-group iterations

    for (int it = blockIdx.x; it < niter; it += gridDim.x) {
        int cid0 = it * 2;
        int b  = cid0 / SPTS;
        int s0 = cid0 % SPTS;

        if (t < NK) sidx[t] = g_idx[(size_t)cid0 * KNB + t];
        __syncthreads();

        // ---- gather into bufA[c][k] : c=0..2 rel-xyz, c=3..66 features ----
        {
            int k = t >> 2;        // 0..63
            int j = t & 3;         // chunk selector
            int g = k >> 5;        // which group
            int n = sidx[k];
            const float4* fr = (const float4*)(g_featT + ((size_t)b * NPTS + n) * CH);
            #pragma unroll
            for (int m = 0; m < 4; m++) {
                float4 v = fr[j + 4*m];
                int cb = 3 + 4*j + 16*m;
                bufA[(cb+0)*STRIDE + k] = v.x;
                bufA[(cb+1)*STRIDE + k] = v.y;
                bufA[(cb+2)*STRIDE + k] = v.z;
                bufA[(cb+3)*STRIDE + k] = v.w;
            }
            if (t < NK) {
                int kk = t;
                int gg = kk >> 5;
                int n2 = sidx[kk];
                const float4* xb4 = g_xyzw + (size_t)b * NPTS;
                float4 pc = xb4[s0 + gg];
                float4 pn = xb4[n2];
                bufA[0*STRIDE + kk] = pn.x - pc.x;
                bufA[1*STRIDE + kk] = pn.y - pc.y;
                bufA[2*STRIDE + kk] = pn.z - pc.z;
            }
        }
        __syncthreads();

        // ---- layer 1: [64x67] @ [67x64] -> relu -> bufB ----
        {
            int k  = t & 63;
            int d0 = (t >> 6) << 4;     // 16 outputs per thread
            uint64_t acc[8];
            {
                const ulonglong2* bb = (const ulonglong2*)(sm + OFF_B1 + d0);
                #pragma unroll
                for (int i = 0; i < 4; i++) { ulonglong2 v = bb[i]; acc[2*i]=v.x; acc[2*i+1]=v.y; }
            }
            const float* wbase = sm + OFF_W1 + d0;
            #pragma unroll 4
            for (int c = 0; c < 67; c++) {
                uint64_t gv2 = pack2(bufA[c*STRIDE + k]);
                const ulonglong2* w = (const ulonglong2*)(wbase + c*64);
                #pragma unroll
                for (int i = 0; i < 4; i++) {
                    ulonglong2 wv = w[i];
                    ffma2(acc[2*i],   gv2, wv.x);
                    ffma2(acc[2*i+1], gv2, wv.y);
                }
            }
            #pragma unroll
            for (int i = 0; i < 8; i++) {
                float lo, hi; unpack2(acc[i], lo, hi);
                bufB[(d0+2*i  )*STRIDE + k] = fmaxf(lo, 0.0f);
                bufB[(d0+2*i+1)*STRIDE + k] = fmaxf(hi, 0.0f);
            }
        }
        __syncthreads();

        // ---- layer 2: [64x64] @ [64x64] -> relu -> bufA (rows 0..63) ----
        {
            int k  = t & 63;
            int d0 = (t >> 6) << 4;
            uint64_t acc[8];
            {
                const ulonglong2* bb = (const ulonglong2*)(sm + OFF_B2 + d0);
                #pragma unroll
                for (int i = 0; i < 4; i++) { ulonglong2 v = bb[i]; acc[2*i]=v.x; acc[2*i+1]=v.y; }
            }
            const float* wbase = sm + OFF_W2 + d0;
            #pragma unroll 4
            for (int c = 0; c < 64; c++) {
                uint64_t gv2 = pack2(bufB[c*STRIDE + k]);
                const ulonglong2* w = (const ulonglong2*)(wbase + c*64);
                #pragma unroll
                for (int i = 0; i < 4; i++) {
                    ulonglong2 wv = w[i];
                    ffma2(acc[2*i],   gv2, wv.x);
                    ffma2(acc[2*i+1], gv2, wv.y);
                }
            }
            #pragma unroll
            for (int i = 0; i < 8; i++) {
                float lo, hi; unpack2(acc[i], lo, hi);
                bufA[(d0+2*i  )*STRIDE + k] = fmaxf(lo, 0.0f);
                bufA[(d0+2*i+1)*STRIDE + k] = fmaxf(hi, 0.0f);
            }
        }
        __syncthreads();

        // ---- layer 3: [32x64] @ [64x128] per group -> relu -> maxpool ----
        // W3 read from global (warp-uniform broadcast loads, L1/L2-cached).
        #pragma unroll
        for (int g = 0; g < 2; g++) {
            int k32 = t & 31;
            int kk  = g * 32 + k32;
            int d0  = (t >> 5) << 4;    // 8 warps * 16 = 128 d
            uint64_t acc[8];
            {
                const ulonglong2* bb = (const ulonglong2*)(sm + OFF_B3 + d0);
                #pragma unroll
                for (int i = 0; i < 4; i++) { ulonglong2 v = bb[i]; acc[2*i]=v.x; acc[2*i+1]=v.y; }
            }
            const float* wbase = W3 + d0;
            #pragma unroll 4
            for (int c = 0; c < 64; c++) {
                uint64_t gv2 = pack2(bufA[c*STRIDE + kk]);
                const ulonglong2* w = (const ulonglong2*)(wbase + c*128);
                #pragma unroll
                for (int i = 0; i < 4; i++) {
                    ulonglong2 wv = w[i];
                    ffma2(acc[2*i],   gv2, wv.x);
                    ffma2(acc[2*i+1], gv2, wv.y);
                }
            }
            int s = s0 + g;
            #pragma unroll
            for (int i = 0; i < 8; i++) {
                float lo, hi; unpack2(acc[i], lo, hi);
                lo = fmaxf(lo, 0.0f);
                hi = fmaxf(hi, 0.0f);
                #pragma unroll
                for (int sh = 16; sh >= 1; sh >>= 1) {
                    lo = fmaxf(lo, __shfl_xor_sync(0xffffffffu, lo, sh));
                    hi = fmaxf(hi, __shfl_xor_sync(0xffffffffu, hi, sh));
                }
                if (lane == 0) {
                    out[OFF_FEAT + ((size_t)b * OUTC + d0 + 2*i    ) * SPTS + s] = lo;
                    out[OFF_FEAT + ((size_t)b * OUTC + d0 + 2*i + 1) * SPTS + s] = hi;
                }
            }
        }
        __syncthreads();
    }
}

// ---------------------------------------------------------------------------
extern "C" void kernel_launch(void* const* d_in, const int* in_sizes, int n_in,
                              void* d_out, int out_size) {
    const float* xyz      = (const float*)d_in[0];
    const float* features = (const float*)d_in[1];
    const float* W1 = (const float*)d_in[2];
    const float* b1 = (const float*)d_in[3];
    const float* W2 = (const float*)d_in[4];
    const float* b2 = (const float*)d_in[5];
    const float* W3 = (const float*)d_in[6];
    const float* b3 = (const float*)d_in[7];
    float* out = (float*)d_out;

    // pack xyz + |p|^2
    prep_kernel<<<(BATCH*NPTS + 255)/256, 256>>>(xyz);

    // ball query: one warp per centroid
    bq_kernel<<<(BATCH*SPTS*32)/256, 256>>>();

    // feature transpose [B,C,N] -> [B,N,C]
    {
        dim3 g(NPTS/32, CH/32, BATCH);
        dim3 blk(32, 8);
        transpose_kernel<<<g, blk>>>(features);
    }

    // trivial outputs
    misc_kernel<<<(N_XYZ_OUT + 255)/256, 256>>>(xyz, out);

    // MLP + maxpool (3 CTAs/SM)
    static bool attr_done = false;
    if (!attr_done) {
        cudaFuncSetAttribute(mlp_kernel, cudaFuncAttributeMaxDynamicSharedMemorySize, SMEM_BYTES);
        attr_done = true;
    }
    mlp_kernel<<<444, MLP_THREADS, SMEM_BYTES>>>(W1, b1, W2, b2, W3, b3, out);
}

// round 7
// speedup vs baseline: 1.2954x; 1.2954x over previous
#include <cuda_runtime.h>
#include <cstdint>

// Problem constants (fixed by the dataset)
#define BATCH 2
#define NPTS  16384
#define CH    64
#define SPTS  4096        // npoint
#define KNB   32          // nsample
#define R2    0.16f       // 0.4^2
#define OUTC  128

#define N_XYZ_OUT  (BATCH*SPTS*3)          // 24576
#define N_FEAT_OUT (BATCH*OUTC*SPTS)       // 1048576
#define OFF_FEAT   N_XYZ_OUT
#define OFF_SAMP   (N_XYZ_OUT + N_FEAT_OUT)

// Scratch (no allocation allowed -> device globals)
__device__ int g_idx[BATCH*SPTS*KNB];
__device__ __align__(16) float g_featT[(size_t)BATCH*NPTS*CH];
__device__ __align__(16) float4 g_xyzw[BATCH*NPTS];

// ---------------------------------------------------------------------------
// f32x2 packed-FMA helpers (sm_103a FFMA2)
// ---------------------------------------------------------------------------
__device__ __forceinline__ void ffma2(uint64_t& acc, uint64_t a, uint64_t b) {
    asm("fma.rn.f32x2 %0, %1, %2, %3;" : "=l"(acc) : "l"(a), "l"(b), "l"(acc));
}
__device__ __forceinline__ uint64_t pack2(float v) {
    uint64_t r;
    asm("mov.b64 %0, {%1, %1};" : "=l"(r) : "r"(__float_as_uint(v)));
    return r;
}
__device__ __forceinline__ uint64_t packab(float a, float b) {
    uint64_t r;
    asm("mov.b64 %0, {%1, %2};" : "=l"(r) : "r"(__float_as_uint(a)), "r"(__float_as_uint(b)));
    return r;
}
__device__ __forceinline__ void unpack2(uint64_t p, float& lo, float& hi) {
    unsigned a, b;
    asm("mov.b64 {%0, %1}, %2;" : "=r"(a), "=r"(b) : "l"(p));
    lo = __uint_as_float(a); hi = __uint_as_float(b);
}

// ---------------------------------------------------------------------------
// Kernel 0: pack xyz + precomputed squared norm into float4
// ---------------------------------------------------------------------------
__global__ void prep_kernel(const float* __restrict__ xyz) {
    int i = blockIdx.x * blockDim.x + threadIdx.x;
    if (i >= BATCH * NPTS) return;
    float px = xyz[i*3+0], py = xyz[i*3+1], pz = xyz[i*3+2];
    float pp = px*px + py*py + pz*pz;
    g_xyzw[i] = make_float4(px, py, pz, pp);
}

// ---------------------------------------------------------------------------
// Kernel 1: ball query. One warp per centroid, early exit at 32 hits.
// Software-pipelined: prefetch next candidate tile to hide L2 latency.
// ---------------------------------------------------------------------------
__global__ void bq_kernel() {
    int w    = (blockIdx.x * blockDim.x + threadIdx.x) >> 5;
    int lane = threadIdx.x & 31;
    if (w >= BATCH * SPTS) return;
    int b = w / SPTS, s = w % SPTS;
    const float4* xb4 = g_xyzw + (size_t)b * NPTS;
    float4 q = xb4[s];
    int* idx = g_idx + (size_t)w * KNB;
    int cnt = 0;
    int firstIdx = 0;
    bool haveFirst = false;
    float4 p = xb4[lane];                       // prime the pipeline
    for (int j0 = 0; j0 < NPTS && cnt < KNB; j0 += 32) {
        float4 pn;
        if (j0 + 32 < NPTS) pn = xb4[j0 + 32 + lane];   // prefetch next tile
        int j = j0 + lane;
        float dot = q.x*p.x + q.y*p.y + q.z*p.z;
        float d2  = q.w + p.w - 2.0f*dot;       // same formula as reference
        bool hit = d2 < R2;
        unsigned mask = __ballot_sync(0xffffffffu, hit);
        if (mask && !haveFirst) {
            firstIdx = __shfl_sync(0xffffffffu, j, __ffs(mask) - 1);
            haveFirst = true;
        }
        int pos = cnt + __popc(mask & ((1u << lane) - 1u));
        if (hit && pos < KNB) idx[pos] = j;
        cnt += __popc(mask);
        p = pn;
    }
    if (cnt < KNB && lane >= cnt) idx[lane] = firstIdx;
}

// ---------------------------------------------------------------------------
// Kernel 2: transpose features [B,C,N] -> [B,N,C]
// ---------------------------------------------------------------------------
__global__ void transpose_kernel(const float* __restrict__ f) {
    __shared__ float tile[32][33];
    int b  = blockIdx.z;
    int c0 = blockIdx.y * 32;
    int n0 = blockIdx.x * 32;
    int tx = threadIdx.x, ty = threadIdx.y;
    const float* src = f + ((size_t)b * CH) * NPTS;
    #pragma unroll
    for (int r = ty; r < 32; r += 8)
        tile[r][tx] = src[(size_t)(c0 + r) * NPTS + n0 + tx];
    __syncthreads();
    float* dst = g_featT + ((size_t)b * NPTS) * CH;
    #pragma unroll
    for (int r = ty; r < 32; r += 8)
        dst[(size_t)(n0 + r) * CH + c0 + tx] = tile[tx][r];
}

// ---------------------------------------------------------------------------
// Kernel 3: trivial outputs
// ---------------------------------------------------------------------------
__global__ void misc_kernel(const float* __restrict__ xyz, float* __restrict__ out) {
    int i = blockIdx.x * blockDim.x + threadIdx.x;
    if (i < N_XYZ_OUT) {
        int b = i / (SPTS * 3), r = i % (SPTS * 3);
        out[i] = xyz[(size_t)b * NPTS * 3 + r];
    }
    if (i < BATCH * SPTS) {
        out[OFF_SAMP + i] = (float)(i % SPTS);
    }
}

// ---------------------------------------------------------------------------
// Kernel 4: gather + 3-layer MLP + maxpool, warp-per-centroid.
// Lane = neighbor k. Activations live entirely in registers (packed f32x2);
// each layer's output feeds the next layer in the SAME thread -> no smem
// activations, no barriers in the mainloop. Weights + biases in smem,
// accessed as warp-uniform LDS.128 broadcasts. All math is FFMA2.
// ---------------------------------------------------------------------------
#define MLP_THREADS 256   // 8 warps -> 8 centroids per block

// smem layout (floats)
#define OFF_W1  0                        // 67*64 = 4288
#define OFF_W2  (OFF_W1 + 67*64)         // +4096
#define OFF_W3  (OFF_W2 + 64*64)         // +8192
#define OFF_B1  (OFF_W3 + 64*128)        // 16576
#define OFF_B2  (OFF_B1 + 64)
#define OFF_B3  (OFF_B2 + 64)
#define SMEM_FLOATS (OFF_B3 + 128)       // 16832
#define SMEM_BYTES  (SMEM_FLOATS * 4)    // 67328 B

__global__ void __launch_bounds__(MLP_THREADS)
mlp_kernel(const float* __restrict__ W1, const float* __restrict__ b1,
           const float* __restrict__ W2, const float* __restrict__ b2,
           const float* __restrict__ W3, const float* __restrict__ b3,
           float* __restrict__ out) {
    extern __shared__ float sm[];
    int t = threadIdx.x;
    // stage all weights + biases once
    for (int i = t; i < 67*64;  i += MLP_THREADS) sm[OFF_W1 + i] = W1[i];
    for (int i = t; i < 64*64;  i += MLP_THREADS) sm[OFF_W2 + i] = W2[i];
    for (int i = t; i < 64*128; i += MLP_THREADS) sm[OFF_W3 + i] = W3[i];
    if (t < 64)  sm[OFF_B1 + t] = b1[t];
    if (t < 64)  sm[OFF_B2 + t] = b2[t];
    if (t < 128) sm[OFF_B3 + t] = b3[t];
    __syncthreads();

    int warp = blockIdx.x * (MLP_THREADS/32) + (t >> 5);   // centroid id
    int lane = t & 31;                                     // neighbor k
    int b = warp / SPTS, s = warp % SPTS;

    // ---- gather: this lane's neighbor point ----
    int n = g_idx[(size_t)warp * KNB + lane];
    uint64_t h[32];   // 64 packed activation channels
    {
        const ulonglong2* fr = (const ulonglong2*)(g_featT + ((size_t)b * NPTS + n) * CH);
        #pragma unroll
        for (int i = 0; i < 16; i++) { ulonglong2 v = fr[i]; h[2*i] = v.x; h[2*i+1] = v.y; }
    }
    float4 pc = g_xyzw[(size_t)b * NPTS + s];
    float4 pn = g_xyzw[(size_t)b * NPTS + n];
    float gx = pn.x - pc.x, gy = pn.y - pc.y, gz = pn.z - pc.z;

    uint64_t acc[32];  // 64 packed outputs

    // ================= layer 1: 67 -> 64 =================
    {
        const ulonglong2* bb = (const ulonglong2*)(sm + OFF_B1);
        #pragma unroll
        for (int i = 0; i < 16; i++) { ulonglong2 v = bb[i]; acc[2*i] = v.x; acc[2*i+1] = v.y; }
    }
    {
        float gxyz[3] = {gx, gy, gz};
        #pragma unroll
        for (int c = 0; c < 3; c++) {
            uint64_t g2 = pack2(gxyz[c]);
            const ulonglong2* w = (const ulonglong2*)(sm + OFF_W1 + c*64);
            #pragma unroll
            for (int i = 0; i < 16; i++) {
                ulonglong2 wv = w[i];
                ffma2(acc[2*i],   g2, wv.x);
                ffma2(acc[2*i+1], g2, wv.y);
            }
        }
    }
    #pragma unroll 2
    for (int cp = 0; cp < 32; cp++) {
        float lo, hi; unpack2(h[cp], lo, hi);
        uint64_t glo = pack2(lo), ghi = pack2(hi);
        const ulonglong2* w0 = (const ulonglong2*)(sm + OFF_W1 + (3 + 2*cp)*64);
        const ulonglong2* w1 = (const ulonglong2*)(sm + OFF_W1 + (4 + 2*cp)*64);
        #pragma unroll
        for (int i = 0; i < 16; i++) {
            ulonglong2 wv = w0[i];
            ffma2(acc[2*i],   glo, wv.x);
            ffma2(acc[2*i+1], glo, wv.y);
        }
        #pragma unroll
        for (int i = 0; i < 16; i++) {
            ulonglong2 wv = w1[i];
            ffma2(acc[2*i],   ghi, wv.x);
            ffma2(acc[2*i+1], ghi, wv.y);
        }
    }
    #pragma unroll
    for (int i = 0; i < 32; i++) {
        float lo, hi; unpack2(acc[i], lo, hi);
        h[i] = packab(fmaxf(lo, 0.0f), fmaxf(hi, 0.0f));
    }

    // ================= layer 2: 64 -> 64 =================
    {
        const ulonglong2* bb = (const ulonglong2*)(sm + OFF_B2);
        #pragma unroll
        for (int i = 0; i < 16; i++) { ulonglong2 v = bb[i]; acc[2*i] = v.x; acc[2*i+1] = v.y; }
    }
    #pragma unroll 2
    for (int cp = 0; cp < 32; cp++) {
        float lo, hi; unpack2(h[cp], lo, hi);
        uint64_t glo = pack2(lo), ghi = pack2(hi);
        const ulonglong2* w0 = (const ulonglong2*)(sm + OFF_W2 + (2*cp    )*64);
        const ulonglong2* w1 = (const ulonglong2*)(sm + OFF_W2 + (2*cp + 1)*64);
        #pragma unroll
        for (int i = 0; i < 16; i++) {
            ulonglong2 wv = w0[i];
            ffma2(acc[2*i],   glo, wv.x);
            ffma2(acc[2*i+1], glo, wv.y);
        }
        #pragma unroll
        for (int i = 0; i < 16; i++) {
            ulonglong2 wv = w1[i];
            ffma2(acc[2*i],   ghi, wv.x);
            ffma2(acc[2*i+1], ghi, wv.y);
        }
    }
    #pragma unroll
    for (int i = 0; i < 32; i++) {
        float lo, hi; unpack2(acc[i], lo, hi);
        h[i] = packab(fmaxf(lo, 0.0f), fmaxf(hi, 0.0f));
    }

    // ================= layer 3: 64 -> 128, fused relu + maxpool =================
    #pragma unroll 1
    for (int half = 0; half < 2; half++) {
        {
            const ulonglong2* bb = (const ulonglong2*)(sm + OFF_B3 + half*64);
            #pragma unroll
            for (int i = 0; i < 16; i++) { ulonglong2 v = bb[i]; acc[2*i] = v.x; acc[2*i+1] = v.y; }
        }
        #pragma unroll 2
        for (int cp = 0; cp < 32; cp++) {
            float lo, hi; unpack2(h[cp], lo, hi);
            uint64_t glo = pack2(lo), ghi = pack2(hi);
            const ulonglong2* w0 = (const ulonglong2*)(sm + OFF_W3 + (2*cp    )*128 + half*64);
            const ulonglong2* w1 = (const ulonglong2*)(sm + OFF_W3 + (2*cp + 1)*128 + half*64);
            #pragma unroll
            for (int i = 0; i < 16; i++) {
                ulonglong2 wv = w0[i];
                ffma2(acc[2*i],   glo, wv.x);
                ffma2(acc[2*i+1], glo, wv.y);
            }
            #pragma unroll
            for (int i = 0; i < 16; i++) {
                ulonglong2 wv = w1[i];
                ffma2(acc[2*i],   ghi, wv.x);
                ffma2(acc[2*i+1], ghi, wv.y);
            }
        }
        // relu + warp maxpool over k + store
        #pragma unroll
        for (int i = 0; i < 32; i++) {
            float lo, hi; unpack2(acc[i], lo, hi);
            lo = fmaxf(lo, 0.0f);
            hi = fmaxf(hi, 0.0f);
            #pragma unroll
            for (int sh = 16; sh >= 1; sh >>= 1) {
                lo = fmaxf(lo, __shfl_xor_sync(0xffffffffu, lo, sh));
                hi = fmaxf(hi, __shfl_xor_sync(0xffffffffu, hi, sh));
            }
            if (lane == 0) {
                int d = half*64 + 2*i;
                out[OFF_FEAT + ((size_t)b * OUTC + d    ) * SPTS + s] = lo;
                out[OFF_FEAT + ((size_t)b * OUTC + d + 1) * SPTS + s] = hi;
            }
        }
    }
}

// ---------------------------------------------------------------------------
extern "C" void kernel_launch(void* const* d_in, const int* in_sizes, int n_in,
                              void* d_out, int out_size) {
    const float* xyz      = (const float*)d_in[0];
    const float* features = (const float*)d_in[1];
    const float* W1 = (const float*)d_in[2];
    const float* b1 = (const float*)d_in[3];
    const float* W2 = (const float*)d_in[4];
    const float* b2 = (const float*)d_in[5];
    const float* W3 = (const float*)d_in[6];
    const float* b3 = (const float*)d_in[7];
    float* out = (float*)d_out;

    // pack xyz + |p|^2
    prep_kernel<<<(BATCH*NPTS + 255)/256, 256>>>(xyz);

    // ball query: one warp per centroid
    bq_kernel<<<(BATCH*SPTS*32)/256, 256>>>();

    // feature transpose [B,C,N] -> [B,N,C]
    {
        dim3 g(NPTS/32, CH/32, BATCH);
        dim3 blk(32, 8);
        transpose_kernel<<<g, blk>>>(features);
    }

    // trivial outputs
    misc_kernel<<<(N_XYZ_OUT + 255)/256, 256>>>(xyz, out);

    // MLP + maxpool: warp-per-centroid, 8192 warps total
    static bool attr_done = false;
    if (!attr_done) {
        cudaFuncSetAttribute(mlp_kernel, cudaFuncAttributeMaxDynamicSharedMemorySize, SMEM_BYTES);
        attr_done = true;
    }
    mlp_kernel<<<(BATCH*SPTS)/(MLP_THREADS/32), MLP_THREADS, SMEM_BYTES>>>(W1, b1, W2, b2, W3, b3, out);
}